// round 2
// baseline (speedup 1.0000x reference)
#include <cuda_runtime.h>
#include <cuda_bf16.h>

#define N_NODES_MAX 50000
#define N_EDGES_MAX 800000
#define D 64

// Scratch (static __device__ — no allocations allowed)
__device__ float g_G[N_NODES_MAX * D];        // features @ W1, 12.8 MB
__device__ int   g_hist[N_NODES_MAX];         // per-dst edge counts
__device__ int   g_cursor[N_NODES_MAX];       // exclusive offsets (mutated by scatter)
__device__ int4  g_rec[N_EDGES_MAX];          // (eid, src, dst, pad), dst-sorted, 12.8 MB
__device__ int   g_idx_is64;

// ---------------------------------------------------------------------------
// Node transform G = features @ W1, plus (thread 0) index-dtype detection,
// plus histogram zeroing. One warp computes 4 rows; W1 staged in smem.
// ---------------------------------------------------------------------------
__global__ void node_gemm_kernel(const float* __restrict__ feat,
                                 const float* __restrict__ W1,
                                 int n_nodes,
                                 const long long* __restrict__ src_probe,
                                 int n_edges) {
    __shared__ float Ws[D * D];
    int tid = threadIdx.x;
    int gtid = blockIdx.x * blockDim.x + tid;

    // dtype detection: read first 16 values as int64; if any out of range,
    // the buffer is int32.
    if (gtid == 0) {
        int is64 = 1;
        int m = n_edges < 16 ? n_edges : 16;
        for (int i = 0; i < m; i++) {
            long long v = src_probe[i];
            if (v < 0 || v >= (long long)n_nodes) { is64 = 0; break; }
        }
        g_idx_is64 = is64;
    }
    // zero histogram
    if (gtid < N_NODES_MAX) g_hist[gtid] = 0;

    for (int i = tid; i < D * D; i += blockDim.x) Ws[i] = W1[i];
    __syncthreads();

    int lane = tid & 31;
    int warpGlobal = gtid >> 5;
    int totalWarps = (int)((gridDim.x * blockDim.x) >> 5);

    for (int base = warpGlobal * 4; base < n_nodes; base += totalWarps * 4) {
        float fa[4], fb[4];
#pragma unroll
        for (int r = 0; r < 4; r++) {
            int row = base + r;
            if (row < n_nodes) {
                fa[r] = feat[row * D + lane];
                fb[r] = feat[row * D + 32 + lane];
            } else {
                fa[r] = 0.f; fb[r] = 0.f;
            }
        }
        float a0[4] = {0.f, 0.f, 0.f, 0.f};
        float a1[4] = {0.f, 0.f, 0.f, 0.f};
#pragma unroll
        for (int k = 0; k < 32; k++) {
            float w0 = Ws[k * D + lane];
            float w1 = Ws[k * D + 32 + lane];
#pragma unroll
            for (int r = 0; r < 4; r++) {
                float v = __shfl_sync(0xffffffffu, fa[r], k);
                a0[r] = fmaf(v, w0, a0[r]);
                a1[r] = fmaf(v, w1, a1[r]);
            }
        }
#pragma unroll
        for (int k = 0; k < 32; k++) {
            float w0 = Ws[(k + 32) * D + lane];
            float w1 = Ws[(k + 32) * D + 32 + lane];
#pragma unroll
            for (int r = 0; r < 4; r++) {
                float v = __shfl_sync(0xffffffffu, fb[r], k);
                a0[r] = fmaf(v, w0, a0[r]);
                a1[r] = fmaf(v, w1, a1[r]);
            }
        }
#pragma unroll
        for (int r = 0; r < 4; r++) {
            int row = base + r;
            if (row < n_nodes) {
                g_G[row * D + lane] = a0[r];
                g_G[row * D + 32 + lane] = a1[r];
            }
        }
    }
}

// ---------------------------------------------------------------------------
// Histogram of dst indices.
// ---------------------------------------------------------------------------
__global__ void hist_kernel(const void* __restrict__ dst_idx, int n_edges) {
    int e = blockIdx.x * blockDim.x + threadIdx.x;
    if (e >= n_edges) return;
    int d = g_idx_is64 ? (int)((const long long*)dst_idx)[e]
                       : ((const int*)dst_idx)[e];
    atomicAdd(&g_hist[d], 1);
}

// ---------------------------------------------------------------------------
// Exclusive prefix scan of g_hist -> g_cursor. Single block, 1024 threads,
// 49 elements per thread (1024*49 = 50176 >= 50000).
// ---------------------------------------------------------------------------
__global__ void scan_kernel(int n_nodes) {
    __shared__ int s[1024];
    const int PER = 49;
    int t = threadIdx.x;
    int base = t * PER;

    int sum = 0;
    for (int i = 0; i < PER; i++) {
        int idx = base + i;
        if (idx < n_nodes) sum += g_hist[idx];
    }
    s[t] = sum;
    __syncthreads();
    // inclusive Hillis-Steele scan over the 1024 partial sums
    for (int off = 1; off < 1024; off <<= 1) {
        int v = (t >= off) ? s[t - off] : 0;
        __syncthreads();
        s[t] += v;
        __syncthreads();
    }
    int run = s[t] - sum;  // exclusive prefix for this thread's chunk
    for (int i = 0; i < PER; i++) {
        int idx = base + i;
        if (idx < n_nodes) {
            g_cursor[idx] = run;
            run += g_hist[idx];
        }
    }
}

// ---------------------------------------------------------------------------
// Scatter edges into dst-sorted record array.
// Intra-bucket order depends on atomic timing, but each record is processed
// independently and written to out[eid], so the OUTPUT is deterministic.
// ---------------------------------------------------------------------------
__global__ void scatter_kernel(const void* __restrict__ src_idx,
                               const void* __restrict__ dst_idx,
                               int n_edges) {
    int e = blockIdx.x * blockDim.x + threadIdx.x;
    if (e >= n_edges) return;
    int s, d;
    if (g_idx_is64) {
        s = (int)((const long long*)src_idx)[e];
        d = (int)((const long long*)dst_idx)[e];
    } else {
        s = ((const int*)src_idx)[e];
        d = ((const int*)dst_idx)[e];
    }
    int pos = atomicAdd(&g_cursor[d], 1);
    g_rec[pos] = make_int4(e, s, d, 0);
}

// ---------------------------------------------------------------------------
// Edge kernel over dst-sorted records. 16 lanes per edge, lane owns a float4.
// Persistent blocks over contiguous chunks: consecutive edges share dst,
// so G[dst] / feat[dst] rows hit L1. b1/W2/b2 cached in registers.
// ---------------------------------------------------------------------------
__global__ void edge_kernel(const float* __restrict__ feat,
                            const float* __restrict__ b1,
                            const float* __restrict__ W2,
                            const float* __restrict__ b2,
                            float* __restrict__ out,
                            int n_edges) {
    int l = threadIdx.x & 15;
    int group = threadIdx.x >> 4;           // 0..15 groups per 256-thread block

    float4 bb = __ldg(&((const float4*)b1)[l]);
    float4 w2 = __ldg(&((const float4*)W2)[l]);
    float b2v = __ldg(&b2[0]);

    int per = (n_edges + gridDim.x - 1) / gridDim.x;
    int start = blockIdx.x * per;
    int end = start + per;
    if (end > n_edges) end = n_edges;

    const float4* G4 = (const float4*)g_G;
    const float4* F4 = (const float4*)feat;

    for (int e0 = start + group; e0 < end; e0 += 16) {
        int4 rec = g_rec[e0];
        int eid = rec.x;
        long long s = rec.y;
        long long d = rec.z;

        float4 gs = __ldg(&G4[s * 16 + l]);
        float4 gd = __ldg(&G4[d * 16 + l]);

        float h0 = fmaxf(gs.x - gd.x + bb.x, 0.f);
        float h1 = fmaxf(gs.y - gd.y + bb.y, 0.f);
        float h2 = fmaxf(gs.z - gd.z + bb.z, 0.f);
        float h3 = fmaxf(gs.w - gd.w + bb.w, 0.f);

        float p = h0 * w2.x + h1 * w2.y + h2 * w2.z + h3 * w2.w;
        p += __shfl_xor_sync(0xffffffffu, p, 1, 16);
        p += __shfl_xor_sync(0xffffffffu, p, 2, 16);
        p += __shfl_xor_sync(0xffffffffu, p, 4, 16);
        p += __shfl_xor_sync(0xffffffffu, p, 8, 16);

        float att = fmaxf(p + b2v, 0.f);
        float a = __expf(-att);

        float4 fd = __ldg(&F4[d * 16 + l]);
        float4 o;
        o.x = a * fd.x; o.y = a * fd.y; o.z = a * fd.z; o.w = a * fd.w;
        ((float4*)out)[(long long)eid * 16 + l] = o;
    }
}

// ---------------------------------------------------------------------------
// kernel_launch — inputs (metadata order):
//   0 features [50000,64] f32
//   1 src_idx  [800000]   int64 (or int32, detected)
//   2 dst_idx  [800000]   int64/int32
//   3 W1 [64,64] f32   4 b1 [64] f32   5 W2 [64,1] f32   6 b2 [1] f32
// output: [800000, 64] f32
// ---------------------------------------------------------------------------
extern "C" void kernel_launch(void* const* d_in, const int* in_sizes, int n_in,
                              void* d_out, int out_size) {
    const float* feat = (const float*)d_in[0];
    const void*  src  = d_in[1];
    const void*  dst  = d_in[2];
    const float* W1   = (const float*)d_in[3];
    const float* b1   = (const float*)d_in[4];
    const float* W2   = (const float*)d_in[5];
    const float* b2   = (const float*)d_in[6];
    float* out = (float*)d_out;

    int n_nodes = in_sizes[0] / D;
    int n_edges = in_sizes[1];

    // 1) node GEMM (+ dtype detection + hist zero)
    int gemm_warptasks = (n_nodes + 3) / 4;
    int gemm_blocks = (gemm_warptasks + 7) / 8;   // 8 warps/block
    // ensure enough threads to zero the full histogram too
    int min_blocks = (N_NODES_MAX + 255) / 256;
    if (gemm_blocks < min_blocks) gemm_blocks = min_blocks;
    node_gemm_kernel<<<gemm_blocks, 256>>>(feat, W1, n_nodes,
                                           (const long long*)src, n_edges);

    // 2) histogram of dst
    int eb = (n_edges + 255) / 256;
    hist_kernel<<<eb, 256>>>(dst, n_edges);

    // 3) exclusive scan
    scan_kernel<<<1, 1024>>>(n_nodes);

    // 4) scatter into dst-sorted records
    scatter_kernel<<<eb, 256>>>(src, dst, n_edges);

    // 5) edge compute, persistent blocks (8 per SM x 148 SMs)
    edge_kernel<<<1184, 256>>>(feat, b1, W2, b2, out, n_edges);
}

// round 3
// speedup vs baseline: 1.8662x; 1.8662x over previous
#include <cuda_runtime.h>
#include <cuda_fp16.h>
#include <cuda_bf16.h>

#define N_NODES_MAX 50000
#define D 64

// Scratch: per-node transformed features G = features @ W1, stored fp16 (6.4 MB)
__device__ __half g_Gh[N_NODES_MAX * D];
__device__ int g_idx_is64;

// ---------------------------------------------------------------------------
// Node transform: G[row,:] = features[row,:] @ W1, stored as fp16.
// One warp computes 4 rows; lane owns adjacent output columns (2*lane, 2*lane+1)
// so each lane writes one half2. Also does index-dtype detection on thread 0.
// ---------------------------------------------------------------------------
__global__ void node_gemm_kernel(const float* __restrict__ feat,
                                 const float* __restrict__ W1,
                                 int n_nodes,
                                 const long long* __restrict__ src_probe,
                                 int n_edges) {
    __shared__ float Ws[D * D];
    int tid = threadIdx.x;
    int gtid = blockIdx.x * blockDim.x + tid;

    if (gtid == 0) {
        int is64 = 1;
        int m = n_edges < 16 ? n_edges : 16;
        for (int i = 0; i < m; i++) {
            long long v = src_probe[i];
            if (v < 0 || v >= (long long)n_nodes) { is64 = 0; break; }
        }
        g_idx_is64 = is64;
    }

    for (int i = tid; i < D * D; i += blockDim.x) Ws[i] = W1[i];
    __syncthreads();

    int lane = tid & 31;
    int warpGlobal = gtid >> 5;
    int totalWarps = (int)((gridDim.x * blockDim.x) >> 5);
    int c0 = 2 * lane;       // output column pair owned by this lane

    for (int base = warpGlobal * 4; base < n_nodes; base += totalWarps * 4) {
        float fa[4], fb[4];
#pragma unroll
        for (int r = 0; r < 4; r++) {
            int row = base + r;
            if (row < n_nodes) {
                fa[r] = feat[row * D + lane];
                fb[r] = feat[row * D + 32 + lane];
            } else {
                fa[r] = 0.f; fb[r] = 0.f;
            }
        }
        float a0[4] = {0.f, 0.f, 0.f, 0.f};
        float a1[4] = {0.f, 0.f, 0.f, 0.f};
#pragma unroll
        for (int k = 0; k < 32; k++) {
            float w0 = Ws[k * D + c0];
            float w1 = Ws[k * D + c0 + 1];
#pragma unroll
            for (int r = 0; r < 4; r++) {
                float v = __shfl_sync(0xffffffffu, fa[r], k);
                a0[r] = fmaf(v, w0, a0[r]);
                a1[r] = fmaf(v, w1, a1[r]);
            }
        }
#pragma unroll
        for (int k = 0; k < 32; k++) {
            float w0 = Ws[(k + 32) * D + c0];
            float w1 = Ws[(k + 32) * D + c0 + 1];
#pragma unroll
            for (int r = 0; r < 4; r++) {
                float v = __shfl_sync(0xffffffffu, fb[r], k);
                a0[r] = fmaf(v, w0, a0[r]);
                a1[r] = fmaf(v, w1, a1[r]);
            }
        }
#pragma unroll
        for (int r = 0; r < 4; r++) {
            int row = base + r;
            if (row < n_nodes) {
                __half2 h2 = __floats2half2_rn(a0[r], a1[r]);
                ((__half2*)g_Gh)[row * 32 + lane] = h2;
            }
        }
    }
}

// ---------------------------------------------------------------------------
// Edge kernel: 16 lanes per edge. Lane l owns columns [4l, 4l+4):
//   - loads 4 halves (8 B, one uint2) of G[src] and G[dst]  -> 128 B/row
//   - loads float4 of feat[dst], b1, W2                     -> 256 B/row
//   h   = relu(G[src] - G[dst] + b1)
//   att = relu(h . W2 + b2);  out = exp(-att) * feat[dst]
// Edges processed in eid order -> output stores fully coalesced.
// ---------------------------------------------------------------------------
__global__ void edge_kernel(const float* __restrict__ feat,
                            const void* __restrict__ src_idx,
                            const void* __restrict__ dst_idx,
                            const float* __restrict__ b1,
                            const float* __restrict__ W2,
                            const float* __restrict__ b2,
                            float* __restrict__ out,
                            int n_edges) {
    int gid = blockIdx.x * blockDim.x + threadIdx.x;
    int e = gid >> 4;
    int l = threadIdx.x & 15;
    if (e >= n_edges) return;

    long long s, d;
    if (g_idx_is64) {
        s = ((const long long*)src_idx)[e];
        d = ((const long long*)dst_idx)[e];
    } else {
        s = (long long)((const int*)src_idx)[e];
        d = (long long)((const int*)dst_idx)[e];
    }

    const __half2* G2 = (const __half2*)g_Gh;
    // lane l reads half2 pairs (2l, 2l+1) of the 32-half2 row
    __half2 gs01 = __ldg(&G2[s * 32 + 2 * l]);
    __half2 gs23 = __ldg(&G2[s * 32 + 2 * l + 1]);
    __half2 gd01 = __ldg(&G2[d * 32 + 2 * l]);
    __half2 gd23 = __ldg(&G2[d * 32 + 2 * l + 1]);

    float4 bb = __ldg(&((const float4*)b1)[l]);
    float4 w2 = __ldg(&((const float4*)W2)[l]);

    float2 s01 = __half22float2(gs01);
    float2 s23 = __half22float2(gs23);
    float2 d01 = __half22float2(gd01);
    float2 d23 = __half22float2(gd23);

    float h0 = fmaxf(s01.x - d01.x + bb.x, 0.f);
    float h1 = fmaxf(s01.y - d01.y + bb.y, 0.f);
    float h2 = fmaxf(s23.x - d23.x + bb.z, 0.f);
    float h3 = fmaxf(s23.y - d23.y + bb.w, 0.f);

    float p = h0 * w2.x + h1 * w2.y + h2 * w2.z + h3 * w2.w;
    p += __shfl_xor_sync(0xffffffffu, p, 1, 16);
    p += __shfl_xor_sync(0xffffffffu, p, 2, 16);
    p += __shfl_xor_sync(0xffffffffu, p, 4, 16);
    p += __shfl_xor_sync(0xffffffffu, p, 8, 16);

    float att = fmaxf(p + __ldg(&b2[0]), 0.f);
    float a = __expf(-att);

    float4 fd = __ldg(&((const float4*)feat)[d * 16 + l]);
    float4 o;
    o.x = a * fd.x; o.y = a * fd.y; o.z = a * fd.z; o.w = a * fd.w;
    ((float4*)out)[(long long)e * 16 + l] = o;
}

// ---------------------------------------------------------------------------
// kernel_launch — inputs (metadata order):
//   0 features [50000,64] f32
//   1 src_idx  [800000]   int64 (or int32, detected)
//   2 dst_idx  [800000]   int64/int32
//   3 W1 [64,64] f32   4 b1 [64] f32   5 W2 [64,1] f32   6 b2 [1] f32
// output: [800000, 64] f32
// ---------------------------------------------------------------------------
extern "C" void kernel_launch(void* const* d_in, const int* in_sizes, int n_in,
                              void* d_out, int out_size) {
    const float* feat = (const float*)d_in[0];
    const void*  src  = d_in[1];
    const void*  dst  = d_in[2];
    const float* W1   = (const float*)d_in[3];
    const float* b1   = (const float*)d_in[4];
    const float* W2   = (const float*)d_in[5];
    const float* b2   = (const float*)d_in[6];
    float* out = (float*)d_out;

    int n_nodes = in_sizes[0] / D;
    int n_edges = in_sizes[1];

    int gemm_warptasks = (n_nodes + 3) / 4;
    int gemm_blocks = (gemm_warptasks + 7) / 8;   // 8 warps/block
    node_gemm_kernel<<<gemm_blocks, 256>>>(feat, W1, n_nodes,
                                           (const long long*)src, n_edges);

    long long total_threads = (long long)n_edges * 16;
    int blocks = (int)((total_threads + 255) / 256);
    edge_kernel<<<blocks, 256>>>(feat, src, dst, b1, W2, b2, out, n_edges);
}

// round 4
// speedup vs baseline: 2.1635x; 1.1593x over previous
#include <cuda_runtime.h>
#include <cuda_fp16.h>
#include <cuda_bf16.h>

#define N_NODES_MAX 50000
#define D 64

// Scratch: per-node transformed features G = features @ W1, stored fp16 (6.4 MB)
__device__ __half g_Gh[N_NODES_MAX * D];
__device__ int g_idx_is64;

// ---------------------------------------------------------------------------
// Node transform: G[row,:] = features[row,:] @ W1, stored as fp16.
// One warp computes 4 rows; lane owns columns (2*lane, 2*lane+1) -> one half2.
// Thread 0 also detects index dtype (int64 vs int32).
// ---------------------------------------------------------------------------
__global__ void node_gemm_kernel(const float* __restrict__ feat,
                                 const float* __restrict__ W1,
                                 int n_nodes,
                                 const long long* __restrict__ src_probe,
                                 int n_edges) {
    __shared__ float Ws[D * D];
    int tid = threadIdx.x;
    int gtid = blockIdx.x * blockDim.x + tid;

    if (gtid == 0) {
        int is64 = 1;
        int m = n_edges < 16 ? n_edges : 16;
        for (int i = 0; i < m; i++) {
            long long v = src_probe[i];
            if (v < 0 || v >= (long long)n_nodes) { is64 = 0; break; }
        }
        g_idx_is64 = is64;
    }

    for (int i = tid; i < D * D; i += blockDim.x) Ws[i] = W1[i];
    __syncthreads();

    int lane = tid & 31;
    int warpGlobal = gtid >> 5;
    int totalWarps = (int)((gridDim.x * blockDim.x) >> 5);
    int c0 = 2 * lane;

    for (int base = warpGlobal * 4; base < n_nodes; base += totalWarps * 4) {
        float fa[4], fb[4];
#pragma unroll
        for (int r = 0; r < 4; r++) {
            int row = base + r;
            if (row < n_nodes) {
                fa[r] = feat[row * D + lane];
                fb[r] = feat[row * D + 32 + lane];
            } else {
                fa[r] = 0.f; fb[r] = 0.f;
            }
        }
        float a0[4] = {0.f, 0.f, 0.f, 0.f};
        float a1[4] = {0.f, 0.f, 0.f, 0.f};
#pragma unroll
        for (int k = 0; k < 32; k++) {
            float w0 = Ws[k * D + c0];
            float w1 = Ws[k * D + c0 + 1];
#pragma unroll
            for (int r = 0; r < 4; r++) {
                float v = __shfl_sync(0xffffffffu, fa[r], k);
                a0[r] = fmaf(v, w0, a0[r]);
                a1[r] = fmaf(v, w1, a1[r]);
            }
        }
#pragma unroll
        for (int k = 0; k < 32; k++) {
            float w0 = Ws[(k + 32) * D + c0];
            float w1 = Ws[(k + 32) * D + c0 + 1];
#pragma unroll
            for (int r = 0; r < 4; r++) {
                float v = __shfl_sync(0xffffffffu, fb[r], k);
                a0[r] = fmaf(v, w0, a0[r]);
                a1[r] = fmaf(v, w1, a1[r]);
            }
        }
#pragma unroll
        for (int r = 0; r < 4; r++) {
            int row = base + r;
            if (row < n_nodes) {
                __half2 h2 = __floats2half2_rn(a0[r], a1[r]);
                ((__half2*)g_Gh)[row * 32 + lane] = h2;
            }
        }
    }
}

// ---------------------------------------------------------------------------
// Edge kernel: 8 lanes per edge, persistent grid-stride loop.
//   G lane mapping: lane l owns G columns [8l, 8l+8)  -> one uint4 (16B) per row
//   feat/out lane mapping: lane l owns float4 slots l and l+8
//     -> each LDG.128/STG.128 instruction covers exactly one 128B line per edge
//   b1/W2/b2 hoisted into registers before the loop.
// Edges processed in eid order -> output stores fully coalesced.
// ---------------------------------------------------------------------------
__global__ void edge_kernel(const float* __restrict__ feat,
                            const void* __restrict__ src_idx,
                            const void* __restrict__ dst_idx,
                            const float* __restrict__ b1,
                            const float* __restrict__ W2,
                            const float* __restrict__ b2,
                            float* __restrict__ out,
                            int n_edges) {
    const int l = threadIdx.x & 7;                      // lane within edge group
    const int groupInBlock = threadIdx.x >> 3;          // 32 groups / 256-thr block
    const int totalGroups = (int)gridDim.x * 32;
    int e = (int)blockIdx.x * 32 + groupInBlock;

    // Hoisted params for this lane's G-columns [8l, 8l+8)
    const float4* B14 = (const float4*)b1;
    const float4* W24 = (const float4*)W2;
    float4 b1a = __ldg(&B14[2 * l]);
    float4 b1b = __ldg(&B14[2 * l + 1]);
    float4 w2a = __ldg(&W24[2 * l]);
    float4 w2b = __ldg(&W24[2 * l + 1]);
    float b2v = __ldg(&b2[0]);
    const int is64 = g_idx_is64;

    const uint4* G16 = (const uint4*)g_Gh;      // 8 halves per uint4, 8 per row
    const float4* F4 = (const float4*)feat;     // 16 float4 per row
    float4* O4 = (float4*)out;

    for (; e < n_edges; e += totalGroups) {
        long long s, d;
        if (is64) {
            s = ((const long long*)src_idx)[e];
            d = ((const long long*)dst_idx)[e];
        } else {
            s = (long long)((const int*)src_idx)[e];
            d = (long long)((const int*)dst_idx)[e];
        }

        uint4 gsu = __ldg(&G16[s * 8 + l]);
        uint4 gdu = __ldg(&G16[d * 8 + l]);

        float2 s0 = __half22float2(*(const __half2*)&gsu.x);
        float2 s1 = __half22float2(*(const __half2*)&gsu.y);
        float2 s2 = __half22float2(*(const __half2*)&gsu.z);
        float2 s3 = __half22float2(*(const __half2*)&gsu.w);
        float2 d0 = __half22float2(*(const __half2*)&gdu.x);
        float2 d1 = __half22float2(*(const __half2*)&gdu.y);
        float2 d2 = __half22float2(*(const __half2*)&gdu.z);
        float2 d3 = __half22float2(*(const __half2*)&gdu.w);

        float h0 = fmaxf(s0.x - d0.x + b1a.x, 0.f);
        float h1 = fmaxf(s0.y - d0.y + b1a.y, 0.f);
        float h2 = fmaxf(s1.x - d1.x + b1a.z, 0.f);
        float h3 = fmaxf(s1.y - d1.y + b1a.w, 0.f);
        float h4 = fmaxf(s2.x - d2.x + b1b.x, 0.f);
        float h5 = fmaxf(s2.y - d2.y + b1b.y, 0.f);
        float h6 = fmaxf(s3.x - d3.x + b1b.z, 0.f);
        float h7 = fmaxf(s3.y - d3.y + b1b.w, 0.f);

        float p = h0 * w2a.x;
        p = fmaf(h1, w2a.y, p);
        p = fmaf(h2, w2a.z, p);
        p = fmaf(h3, w2a.w, p);
        p = fmaf(h4, w2b.x, p);
        p = fmaf(h5, w2b.y, p);
        p = fmaf(h6, w2b.z, p);
        p = fmaf(h7, w2b.w, p);

        p += __shfl_xor_sync(0xffffffffu, p, 1, 8);
        p += __shfl_xor_sync(0xffffffffu, p, 2, 8);
        p += __shfl_xor_sync(0xffffffffu, p, 4, 8);

        float att = fmaxf(p + b2v, 0.f);
        float a = __expf(-att);

        // feat/out: lane covers float4 slots l and l+8 (one 128B line per instr)
        float4 fdA = __ldg(&F4[d * 16 + l]);
        float4 fdB = __ldg(&F4[d * 16 + l + 8]);
        float4 oA, oB;
        oA.x = a * fdA.x; oA.y = a * fdA.y; oA.z = a * fdA.z; oA.w = a * fdA.w;
        oB.x = a * fdB.x; oB.y = a * fdB.y; oB.z = a * fdB.z; oB.w = a * fdB.w;
        long long ob = (long long)e * 16;
        O4[ob + l] = oA;
        O4[ob + l + 8] = oB;
    }
}

// ---------------------------------------------------------------------------
// kernel_launch — inputs (metadata order):
//   0 features [50000,64] f32
//   1 src_idx  [800000]   int64 (or int32, detected)
//   2 dst_idx  [800000]   int64/int32
//   3 W1 [64,64] f32   4 b1 [64] f32   5 W2 [64,1] f32   6 b2 [1] f32
// output: [800000, 64] f32
// ---------------------------------------------------------------------------
extern "C" void kernel_launch(void* const* d_in, const int* in_sizes, int n_in,
                              void* d_out, int out_size) {
    const float* feat = (const float*)d_in[0];
    const void*  src  = d_in[1];
    const void*  dst  = d_in[2];
    const float* W1   = (const float*)d_in[3];
    const float* b1   = (const float*)d_in[4];
    const float* W2   = (const float*)d_in[5];
    const float* b2   = (const float*)d_in[6];
    float* out = (float*)d_out;

    int n_nodes = in_sizes[0] / D;
    int n_edges = in_sizes[1];

    int gemm_warptasks = (n_nodes + 3) / 4;
    int gemm_blocks = (gemm_warptasks + 7) / 8;   // 8 warps/block
    node_gemm_kernel<<<gemm_blocks, 256>>>(feat, W1, n_nodes,
                                           (const long long*)src, n_edges);

    // persistent-ish: 1184 blocks (8/SM), 32 edge-groups per block
    edge_kernel<<<1184, 256>>>(feat, src, dst, b1, W2, b2, out, n_edges);
}

// round 5
// speedup vs baseline: 2.5562x; 1.1815x over previous
#include <cuda_runtime.h>
#include <cuda_fp16.h>
#include <cuda_bf16.h>

#define N_NODES_MAX 50000
#define D 64

// Per-node record, 256 B: halves [0..63] = G = feat@W1 (fp16), [64..127] = feat (fp16)
__device__ __half g_rec[N_NODES_MAX * 128];
__device__ int g_idx_is64;

// ---------------------------------------------------------------------------
// Node transform: G[row,:] = features[row,:] @ W1 -> fp16, plus feat -> fp16,
// both into the interleaved record. One warp does 4 rows; lane owns G columns
// (2*lane, 2*lane+1). Thread 0 detects index dtype.
// ---------------------------------------------------------------------------
__global__ void node_gemm_kernel(const float* __restrict__ feat,
                                 const float* __restrict__ W1,
                                 int n_nodes,
                                 const long long* __restrict__ src_probe,
                                 int n_edges) {
    __shared__ float Ws[D * D];
    int tid = threadIdx.x;
    int gtid = blockIdx.x * blockDim.x + tid;

    if (gtid == 0) {
        int is64 = 1;
        int m = n_edges < 16 ? n_edges : 16;
        for (int i = 0; i < m; i++) {
            long long v = src_probe[i];
            if (v < 0 || v >= (long long)n_nodes) { is64 = 0; break; }
        }
        g_idx_is64 = is64;
    }

    for (int i = tid; i < D * D; i += blockDim.x) Ws[i] = W1[i];
    __syncthreads();

    int lane = tid & 31;
    int warpGlobal = gtid >> 5;
    int totalWarps = (int)((gridDim.x * blockDim.x) >> 5);
    int c0 = 2 * lane;

    for (int base = warpGlobal * 4; base < n_nodes; base += totalWarps * 4) {
        float fa[4], fb[4];
#pragma unroll
        for (int r = 0; r < 4; r++) {
            int row = base + r;
            if (row < n_nodes) {
                fa[r] = feat[row * D + lane];
                fb[r] = feat[row * D + 32 + lane];
            } else {
                fa[r] = 0.f; fb[r] = 0.f;
            }
        }
        float a0[4] = {0.f, 0.f, 0.f, 0.f};
        float a1[4] = {0.f, 0.f, 0.f, 0.f};
#pragma unroll
        for (int k = 0; k < 32; k++) {
            float w0 = Ws[k * D + c0];
            float w1 = Ws[k * D + c0 + 1];
#pragma unroll
            for (int r = 0; r < 4; r++) {
                float v = __shfl_sync(0xffffffffu, fa[r], k);
                a0[r] = fmaf(v, w0, a0[r]);
                a1[r] = fmaf(v, w1, a1[r]);
            }
        }
#pragma unroll
        for (int k = 0; k < 32; k++) {
            float w0 = Ws[(k + 32) * D + c0];
            float w1 = Ws[(k + 32) * D + c0 + 1];
#pragma unroll
            for (int r = 0; r < 4; r++) {
                float v = __shfl_sync(0xffffffffu, fb[r], k);
                a0[r] = fmaf(v, w0, a0[r]);
                a1[r] = fmaf(v, w1, a1[r]);
            }
        }
#pragma unroll
        for (int r = 0; r < 4; r++) {
            int row = base + r;
            if (row < n_nodes) {
                // G columns (2l, 2l+1) as one half2
                ((__half2*)g_rec)[row * 64 + lane] = __floats2half2_rn(a0[r], a1[r]);
                // feat fp16: cols lane and lane+32 into record halves [64..127]
                g_rec[row * 128 + 64 + lane] = __float2half_rn(fa[r]);
                g_rec[row * 128 + 96 + lane] = __float2half_rn(fb[r]);
            }
        }
    }
}

// ---------------------------------------------------------------------------
// Edge kernel: 8 lanes per edge, 2 edges per group-iteration (ILP x2).
//   G:   lane l owns cols [8l, 8l+8)  -> one uint4 (16 B)
//   fd:  lane l owns cols [4l,4l+4) and [32+4l,+4) -> two uint2 (8 B) of fp16
//   out: lane l writes float4 slots l and l+8 -> one full 128B line per instr
// Edges in eid order -> stores fully coalesced.
// ---------------------------------------------------------------------------
__global__ void __launch_bounds__(256, 4)
edge_kernel(const void* __restrict__ src_idx,
            const void* __restrict__ dst_idx,
            const float* __restrict__ b1,
            const float* __restrict__ W2,
            const float* __restrict__ b2,
            float* __restrict__ out,
            int n_edges) {
    const int l = threadIdx.x & 7;
    const int groupInBlock = threadIdx.x >> 3;           // 32 groups / block
    const int gid = (int)blockIdx.x * 32 + groupInBlock;
    const int totalGroups = (int)gridDim.x * 32;

    const float4* B14 = (const float4*)b1;
    const float4* W24 = (const float4*)W2;
    float4 b1a = __ldg(&B14[2 * l]);
    float4 b1b = __ldg(&B14[2 * l + 1]);
    float4 w2a = __ldg(&W24[2 * l]);
    float4 w2b = __ldg(&W24[2 * l + 1]);
    float b2v = __ldg(&b2[0]);
    const int is64 = g_idx_is64;

    const uint4* R16 = (const uint4*)g_rec;   // 16 uint4 per node: [0..7]=G, [8..15]=F
    const uint2* R8  = (const uint2*)g_rec;   // 32 uint2 per node
    float4* O4 = (float4*)out;

    for (int e0 = 2 * gid; e0 < n_edges; e0 += 2 * totalGroups) {
        int e1 = e0 + 1;
        bool hasB = (e1 < n_edges);

        long long sA, dA, sB = 0, dB = 0;
        if (is64) {
            sA = ((const long long*)src_idx)[e0];
            dA = ((const long long*)dst_idx)[e0];
            if (hasB) {
                sB = ((const long long*)src_idx)[e1];
                dB = ((const long long*)dst_idx)[e1];
            }
        } else {
            sA = (long long)((const int*)src_idx)[e0];
            dA = (long long)((const int*)dst_idx)[e0];
            if (hasB) {
                sB = (long long)((const int*)src_idx)[e1];
                dB = (long long)((const int*)dst_idx)[e1];
            }
        }

        // Issue all gathers for both edges before any compute.
        uint4 gsA = __ldg(&R16[sA * 16 + l]);
        uint4 gdA = __ldg(&R16[dA * 16 + l]);
        uint2 fdA0 = __ldg(&R8[dA * 32 + 16 + l]);       // feat cols 4l..4l+3
        uint2 fdA1 = __ldg(&R8[dA * 32 + 24 + l]);       // feat cols 32+4l..+3
        uint4 gsB, gdB; uint2 fdB0, fdB1;
        if (hasB) {
            gsB = __ldg(&R16[sB * 16 + l]);
            gdB = __ldg(&R16[dB * 16 + l]);
            fdB0 = __ldg(&R8[dB * 32 + 16 + l]);
            fdB1 = __ldg(&R8[dB * 32 + 24 + l]);
        }

        // ---- edge A ----
        {
            float2 s0 = __half22float2(*(const __half2*)&gsA.x);
            float2 s1 = __half22float2(*(const __half2*)&gsA.y);
            float2 s2 = __half22float2(*(const __half2*)&gsA.z);
            float2 s3 = __half22float2(*(const __half2*)&gsA.w);
            float2 d0 = __half22float2(*(const __half2*)&gdA.x);
            float2 d1 = __half22float2(*(const __half2*)&gdA.y);
            float2 d2 = __half22float2(*(const __half2*)&gdA.z);
            float2 d3 = __half22float2(*(const __half2*)&gdA.w);

            float h0 = fmaxf(s0.x - d0.x + b1a.x, 0.f);
            float h1 = fmaxf(s0.y - d0.y + b1a.y, 0.f);
            float h2 = fmaxf(s1.x - d1.x + b1a.z, 0.f);
            float h3 = fmaxf(s1.y - d1.y + b1a.w, 0.f);
            float h4 = fmaxf(s2.x - d2.x + b1b.x, 0.f);
            float h5 = fmaxf(s2.y - d2.y + b1b.y, 0.f);
            float h6 = fmaxf(s3.x - d3.x + b1b.z, 0.f);
            float h7 = fmaxf(s3.y - d3.y + b1b.w, 0.f);

            float p = h0 * w2a.x;
            p = fmaf(h1, w2a.y, p); p = fmaf(h2, w2a.z, p); p = fmaf(h3, w2a.w, p);
            p = fmaf(h4, w2b.x, p); p = fmaf(h5, w2b.y, p);
            p = fmaf(h6, w2b.z, p); p = fmaf(h7, w2b.w, p);

            p += __shfl_xor_sync(0xffffffffu, p, 1, 8);
            p += __shfl_xor_sync(0xffffffffu, p, 2, 8);
            p += __shfl_xor_sync(0xffffffffu, p, 4, 8);

            float a = __expf(-fmaxf(p + b2v, 0.f));

            float2 f0 = __half22float2(*(const __half2*)&fdA0.x);
            float2 f1 = __half22float2(*(const __half2*)&fdA0.y);
            float2 f2 = __half22float2(*(const __half2*)&fdA1.x);
            float2 f3 = __half22float2(*(const __half2*)&fdA1.y);
            float4 oA = make_float4(a * f0.x, a * f0.y, a * f1.x, a * f1.y);
            float4 oB = make_float4(a * f2.x, a * f2.y, a * f3.x, a * f3.y);
            long long ob = (long long)e0 * 16;
            O4[ob + l] = oA;
            O4[ob + l + 8] = oB;
        }

        // ---- edge B ----
        if (hasB) {
            float2 s0 = __half22float2(*(const __half2*)&gsB.x);
            float2 s1 = __half22float2(*(const __half2*)&gsB.y);
            float2 s2 = __half22float2(*(const __half2*)&gsB.z);
            float2 s3 = __half22float2(*(const __half2*)&gsB.w);
            float2 d0 = __half22float2(*(const __half2*)&gdB.x);
            float2 d1 = __half22float2(*(const __half2*)&gdB.y);
            float2 d2 = __half22float2(*(const __half2*)&gdB.z);
            float2 d3 = __half22float2(*(const __half2*)&gdB.w);

            float h0 = fmaxf(s0.x - d0.x + b1a.x, 0.f);
            float h1 = fmaxf(s0.y - d0.y + b1a.y, 0.f);
            float h2 = fmaxf(s1.x - d1.x + b1a.z, 0.f);
            float h3 = fmaxf(s1.y - d1.y + b1a.w, 0.f);
            float h4 = fmaxf(s2.x - d2.x + b1b.x, 0.f);
            float h5 = fmaxf(s2.y - d2.y + b1b.y, 0.f);
            float h6 = fmaxf(s3.x - d3.x + b1b.z, 0.f);
            float h7 = fmaxf(s3.y - d3.y + b1b.w, 0.f);

            float p = h0 * w2a.x;
            p = fmaf(h1, w2a.y, p); p = fmaf(h2, w2a.z, p); p = fmaf(h3, w2a.w, p);
            p = fmaf(h4, w2b.x, p); p = fmaf(h5, w2b.y, p);
            p = fmaf(h6, w2b.z, p); p = fmaf(h7, w2b.w, p);

            p += __shfl_xor_sync(0xffffffffu, p, 1, 8);
            p += __shfl_xor_sync(0xffffffffu, p, 2, 8);
            p += __shfl_xor_sync(0xffffffffu, p, 4, 8);

            float a = __expf(-fmaxf(p + b2v, 0.f));

            float2 f0 = __half22float2(*(const __half2*)&fdB0.x);
            float2 f1 = __half22float2(*(const __half2*)&fdB0.y);
            float2 f2 = __half22float2(*(const __half2*)&fdB1.x);
            float2 f3 = __half22float2(*(const __half2*)&fdB1.y);
            float4 oA = make_float4(a * f0.x, a * f0.y, a * f1.x, a * f1.y);
            float4 oB = make_float4(a * f2.x, a * f2.y, a * f3.x, a * f3.y);
            long long ob = (long long)e1 * 16;
            O4[ob + l] = oA;
            O4[ob + l + 8] = oB;
        }
    }
}

// ---------------------------------------------------------------------------
// kernel_launch — inputs (metadata order):
//   0 features [50000,64] f32
//   1 src_idx  [800000]   int64 (or int32, detected)
//   2 dst_idx  [800000]   int64/int32
//   3 W1 [64,64] f32   4 b1 [64] f32   5 W2 [64,1] f32   6 b2 [1] f32
// output: [800000, 64] f32
// ---------------------------------------------------------------------------
extern "C" void kernel_launch(void* const* d_in, const int* in_sizes, int n_in,
                              void* d_out, int out_size) {
    const float* feat = (const float*)d_in[0];
    const void*  src  = d_in[1];
    const void*  dst  = d_in[2];
    const float* W1   = (const float*)d_in[3];
    const float* b1   = (const float*)d_in[4];
    const float* W2   = (const float*)d_in[5];
    const float* b2   = (const float*)d_in[6];
    float* out = (float*)d_out;

    int n_nodes = in_sizes[0] / D;
    int n_edges = in_sizes[1];

    int gemm_warptasks = (n_nodes + 3) / 4;
    int gemm_blocks = (gemm_warptasks + 7) / 8;   // 8 warps/block
    node_gemm_kernel<<<gemm_blocks, 256>>>(feat, W1, n_nodes,
                                           (const long long*)src, n_edges);

    edge_kernel<<<1184, 256>>>(src, dst, b1, W2, b2, out, n_edges);
}

// round 6
// speedup vs baseline: 2.5665x; 1.0040x over previous
#include <cuda_runtime.h>
#include <cuda_fp16.h>
#include <cuda_bf16.h>

#define N_NODES_MAX 50000
#define D 64

// Per-node record, 256 B:
//   halves [0..63]   = G = feat@W1 (fp16), natural column order
//   halves [64..127] = feat (fp16), PERMUTED: pos 64+8q+j holds
//                      feat[4q+j] for j<4, feat[32+4q+(j-4)] for j>=4
// so edge-lane l reads G cols [8l..8l+8) and its 8 feat cols each as ONE uint4.
__device__ __half g_rec[N_NODES_MAX * 128];
__device__ int g_idx_is64;

// ---------------------------------------------------------------------------
// Node transform + record build. One warp does 4 rows; lane owns G columns
// (2*lane, 2*lane+1). Thread 0 detects index dtype.
// ---------------------------------------------------------------------------
__global__ void node_gemm_kernel(const float* __restrict__ feat,
                                 const float* __restrict__ W1,
                                 int n_nodes,
                                 const long long* __restrict__ src_probe,
                                 int n_edges) {
    __shared__ float Ws[D * D];
    int tid = threadIdx.x;
    int gtid = blockIdx.x * blockDim.x + tid;

    if (gtid == 0) {
        int is64 = 1;
        int m = n_edges < 16 ? n_edges : 16;
        for (int i = 0; i < m; i++) {
            long long v = src_probe[i];
            if (v < 0 || v >= (long long)n_nodes) { is64 = 0; break; }
        }
        g_idx_is64 = is64;
    }

    for (int i = tid; i < D * D; i += blockDim.x) Ws[i] = W1[i];
    __syncthreads();

    int lane = tid & 31;
    int warpGlobal = gtid >> 5;
    int totalWarps = (int)((gridDim.x * blockDim.x) >> 5);
    int c0 = 2 * lane;
    // permuted feat positions for this lane's two columns (lane, lane+32)
    int posA = 64 + 8 * (lane >> 2) + (lane & 3);
    int posB = posA + 4;

    for (int base = warpGlobal * 4; base < n_nodes; base += totalWarps * 4) {
        float fa[4], fb[4];
#pragma unroll
        for (int r = 0; r < 4; r++) {
            int row = base + r;
            if (row < n_nodes) {
                fa[r] = feat[row * D + lane];
                fb[r] = feat[row * D + 32 + lane];
            } else {
                fa[r] = 0.f; fb[r] = 0.f;
            }
        }
        float a0[4] = {0.f, 0.f, 0.f, 0.f};
        float a1[4] = {0.f, 0.f, 0.f, 0.f};
#pragma unroll
        for (int k = 0; k < 32; k++) {
            float w0 = Ws[k * D + c0];
            float w1 = Ws[k * D + c0 + 1];
#pragma unroll
            for (int r = 0; r < 4; r++) {
                float v = __shfl_sync(0xffffffffu, fa[r], k);
                a0[r] = fmaf(v, w0, a0[r]);
                a1[r] = fmaf(v, w1, a1[r]);
            }
        }
#pragma unroll
        for (int k = 0; k < 32; k++) {
            float w0 = Ws[(k + 32) * D + c0];
            float w1 = Ws[(k + 32) * D + c0 + 1];
#pragma unroll
            for (int r = 0; r < 4; r++) {
                float v = __shfl_sync(0xffffffffu, fb[r], k);
                a0[r] = fmaf(v, w0, a0[r]);
                a1[r] = fmaf(v, w1, a1[r]);
            }
        }
#pragma unroll
        for (int r = 0; r < 4; r++) {
            int row = base + r;
            if (row < n_nodes) {
                ((__half2*)g_rec)[row * 64 + lane] = __floats2half2_rn(a0[r], a1[r]);
                g_rec[row * 128 + posA] = __float2half_rn(fa[r]);
                g_rec[row * 128 + posB] = __float2half_rn(fb[r]);
            }
        }
    }
}

// ---------------------------------------------------------------------------
// Edge kernel: 8 lanes per edge, 2 edges per iteration (ILP x2).
//   gs, gd, fd: one uint4 (16 B) each per lane.
//   h computed in half2 (hsub2/hadd2/hmax2), dot accumulated in fp32.
//   out: lane l writes float4 slots l and l+8 -> full 128B line per instr.
// ---------------------------------------------------------------------------
__global__ void __launch_bounds__(256, 5)
edge_kernel(const void* __restrict__ src_idx,
            const void* __restrict__ dst_idx,
            const float* __restrict__ b1,
            const float* __restrict__ W2,
            const float* __restrict__ b2,
            float* __restrict__ out,
            int n_edges) {
    const int l = threadIdx.x & 7;
    const int groupInBlock = threadIdx.x >> 3;
    const int gid = (int)blockIdx.x * 32 + groupInBlock;
    const int totalGroups = (int)gridDim.x * 32;

    const float4* B14 = (const float4*)b1;
    const float4* W24 = (const float4*)W2;
    float4 b1a = __ldg(&B14[2 * l]);
    float4 b1b = __ldg(&B14[2 * l + 1]);
    float4 w2a = __ldg(&W24[2 * l]);
    float4 w2b = __ldg(&W24[2 * l + 1]);
    float b2v = __ldg(&b2[0]);
    __half2 hb0 = __floats2half2_rn(b1a.x, b1a.y);
    __half2 hb1 = __floats2half2_rn(b1a.z, b1a.w);
    __half2 hb2 = __floats2half2_rn(b1b.x, b1b.y);
    __half2 hb3 = __floats2half2_rn(b1b.z, b1b.w);
    const __half2 hz = __float2half2_rn(0.f);
    const int is64 = g_idx_is64;

    const uint4* R16 = (const uint4*)g_rec;   // 16 uint4/node: [0..7]=G, [8..15]=F(perm)
    float4* O4 = (float4*)out;

    for (int e0 = 2 * gid; e0 < n_edges; e0 += 2 * totalGroups) {
        int e1 = e0 + 1;
        bool hasB = (e1 < n_edges);

        long long sA, dA, sB = 0, dB = 0;
        if (is64) {
            longlong2 sp = __ldg(&((const longlong2*)src_idx)[e0 >> 1]);
            longlong2 dp = __ldg(&((const longlong2*)dst_idx)[e0 >> 1]);
            sA = sp.x; dA = dp.x; sB = sp.y; dB = dp.y;
        } else {
            int2 sp = __ldg(&((const int2*)src_idx)[e0 >> 1]);
            int2 dp = __ldg(&((const int2*)dst_idx)[e0 >> 1]);
            sA = sp.x; dA = dp.x; sB = sp.y; dB = dp.y;
        }

        // Issue all gathers for both edges before compute.
        uint4 gsA = __ldg(&R16[sA * 16 + l]);
        uint4 gdA = __ldg(&R16[dA * 16 + l]);
        uint4 fdA = __ldg(&R16[dA * 16 + 8 + l]);
        uint4 gsB, gdB, fdB;
        if (hasB) {
            gsB = __ldg(&R16[sB * 16 + l]);
            gdB = __ldg(&R16[dB * 16 + l]);
            fdB = __ldg(&R16[dB * 16 + 8 + l]);
        }

#define EDGE_BODY(GS, GD, FD, EIDX)                                            \
        {                                                                      \
            __half2 h0 = __hmax2(__hadd2(__hsub2(*(const __half2*)&GS.x,       \
                                                 *(const __half2*)&GD.x), hb0), hz); \
            __half2 h1 = __hmax2(__hadd2(__hsub2(*(const __half2*)&GS.y,       \
                                                 *(const __half2*)&GD.y), hb1), hz); \
            __half2 h2 = __hmax2(__hadd2(__hsub2(*(const __half2*)&GS.z,       \
                                                 *(const __half2*)&GD.z), hb2), hz); \
            __half2 h3 = __hmax2(__hadd2(__hsub2(*(const __half2*)&GS.w,       \
                                                 *(const __half2*)&GD.w), hb3), hz); \
            float2 p0 = __half22float2(h0);                                    \
            float2 p1 = __half22float2(h1);                                    \
            float2 p2 = __half22float2(h2);                                    \
            float2 p3 = __half22float2(h3);                                    \
            float p = p0.x * w2a.x;                                            \
            p = fmaf(p0.y, w2a.y, p); p = fmaf(p1.x, w2a.z, p);                \
            p = fmaf(p1.y, w2a.w, p); p = fmaf(p2.x, w2b.x, p);                \
            p = fmaf(p2.y, w2b.y, p); p = fmaf(p3.x, w2b.z, p);                \
            p = fmaf(p3.y, w2b.w, p);                                          \
            p += __shfl_xor_sync(0xffffffffu, p, 1, 8);                        \
            p += __shfl_xor_sync(0xffffffffu, p, 2, 8);                        \
            p += __shfl_xor_sync(0xffffffffu, p, 4, 8);                        \
            float a = __expf(-fmaxf(p + b2v, 0.f));                            \
            float2 f0 = __half22float2(*(const __half2*)&FD.x);                \
            float2 f1 = __half22float2(*(const __half2*)&FD.y);                \
            float2 f2 = __half22float2(*(const __half2*)&FD.z);                \
            float2 f3 = __half22float2(*(const __half2*)&FD.w);                \
            float4 oA = make_float4(a * f0.x, a * f0.y, a * f1.x, a * f1.y);   \
            float4 oB = make_float4(a * f2.x, a * f2.y, a * f3.x, a * f3.y);   \
            long long ob = (long long)(EIDX) * 16;                             \
            O4[ob + l] = oA;                                                   \
            O4[ob + l + 8] = oB;                                               \
        }

        EDGE_BODY(gsA, gdA, fdA, e0)
        if (hasB) EDGE_BODY(gsB, gdB, fdB, e1)
#undef EDGE_BODY
    }
}

// ---------------------------------------------------------------------------
// kernel_launch — inputs (metadata order):
//   0 features [50000,64] f32
//   1 src_idx  [800000]   int64 (or int32, detected)
//   2 dst_idx  [800000]   int64/int32
//   3 W1 [64,64] f32   4 b1 [64] f32   5 W2 [64,1] f32   6 b2 [1] f32
// output: [800000, 64] f32
// ---------------------------------------------------------------------------
extern "C" void kernel_launch(void* const* d_in, const int* in_sizes, int n_in,
                              void* d_out, int out_size) {
    const float* feat = (const float*)d_in[0];
    const void*  src  = d_in[1];
    const void*  dst  = d_in[2];
    const float* W1   = (const float*)d_in[3];
    const float* b1   = (const float*)d_in[4];
    const float* W2   = (const float*)d_in[5];
    const float* b2   = (const float*)d_in[6];
    float* out = (float*)d_out;

    int n_nodes = in_sizes[0] / D;
    int n_edges = in_sizes[1];

    int gemm_warptasks = (n_nodes + 3) / 4;
    int gemm_blocks = (gemm_warptasks + 7) / 8;   // 8 warps/block
    node_gemm_kernel<<<gemm_blocks, 256>>>(feat, W1, n_nodes,
                                           (const long long*)src, n_edges);

    edge_kernel<<<1184, 256>>>(src, dst, b1, W2, b2, out, n_edges);
}